// round 14
// baseline (speedup 1.0000x reference)
#include <cuda_runtime.h>
#include <cuda_bf16.h>
#include <cstdint>

#define NT 192
#define CHUNK 16

__device__ int g_seg[2000128];

// fused weight quads: entry (n,kt,i4) = 16B {bh0,bh1,bl0,bl1}
// W1 row stride 192B (12 quads); W2/W3 row stride 320B (20 quads)
#define OFF_W1   0        // 64*192 = 12288
#define OFF_W2   12288    // 64*320 = 20480
#define OFF_W3   32768    // 32*320 = 10240
#define OFF_B1   43008
#define OFF_B2   43264
#define OFF_B3   43520
#define OFF_FLUSH 43648   // 6 warps * 16*33*4 = 12672
#define SMEM_BYTES 56320

static __device__ __forceinline__ void mma_bf16(float c[4], const uint32_t a[4],
                                                uint32_t b0, uint32_t b1) {
    asm volatile(
        "mma.sync.aligned.m16n8k16.row.col.f32.bf16.bf16.f32 "
        "{%0,%1,%2,%3}, {%4,%5,%6,%7}, {%8,%9}, {%0,%1,%2,%3};"
        : "+f"(c[0]), "+f"(c[1]), "+f"(c[2]), "+f"(c[3])
        : "r"(a[0]), "r"(a[1]), "r"(a[2]), "r"(a[3]), "r"(b0), "r"(b1));
}
static __device__ __forceinline__ uint32_t pack_hi(float v0, float v1) {
    return __byte_perm(__float_as_uint(v0), __float_as_uint(v1), 0x7632);
}
static __device__ __forceinline__ uint32_t pack_lo(float v0, float v1) {
    float h0 = __uint_as_float(__float_as_uint(v0) & 0xFFFF0000u);
    float h1 = __uint_as_float(__float_as_uint(v1) & 0xFFFF0000u);
    __nv_bfloat162 p = __floats2bfloat162_rn(v0 - h0, v1 - h1);
    return *(uint32_t*)&p;
}
// 3-pass split MMA: hi*hi + hi*lo + lo*hi (fp32-accurate to ~2^-18)
static __device__ __forceinline__ void mma3(float c[4], const uint32_t ah[4],
                                            const uint32_t al[4], uint4 q) {
    mma_bf16(c, ah, q.x, q.y);
    mma_bf16(c, ah, q.z, q.w);
    mma_bf16(c, al, q.x, q.y);
}
static __device__ __forceinline__ void repack(const float* s0, const float* s1,
                                              uint32_t ah[4], uint32_t al[4]) {
    ah[0] = pack_hi(s0[0], s0[1]);  al[0] = pack_lo(s0[0], s0[1]);
    ah[1] = pack_hi(s0[2], s0[3]);  al[1] = pack_lo(s0[2], s0[3]);
    ah[2] = pack_hi(s1[0], s1[1]);  al[2] = pack_lo(s1[0], s1[1]);
    ah[3] = pack_hi(s1[2], s1[3]);  al[3] = pack_lo(s1[2], s1[3]);
}
static __device__ __forceinline__ float2 load_in(const float* __restrict__ x,
                                                 const float* __restrict__ h,
                                                 int row, int kk, int N) {
    float2 v = make_float2(0.f, 0.f);
    if (row < N) {
        if (kk < 8)       v = *(const float2*)(x + (size_t)row * 8 + kk);
        else if (kk < 40) v = *(const float2*)(h + (size_t)row * 32 + (kk - 8));
    }
    return v;
}
static __device__ __forceinline__ void prefetch_chunk(const float* __restrict__ x,
                                                      const float* __restrict__ h,
                                                      int base, int N, int r4, int i4,
                                                      float2 pA[6], float2 pB[6]) {
    #pragma unroll
    for (int kt = 0; kt < 3; kt++)
        #pragma unroll
        for (int p = 0; p < 2; p++) {
            int kk = kt * 16 + 2 * i4 + 8 * p;
            pA[kt * 2 + p] = load_in(x, h, base + r4, kk, N);
            pB[kt * 2 + p] = load_in(x, h, base + 8 + r4, kk, N);
        }
}

__global__ void init_kernel(const int* __restrict__ ptr, float* __restrict__ out,
                            int out_size, int M) {
    int tid = blockIdx.x * blockDim.x + threadIdx.x;
    int nth = gridDim.x * blockDim.x;
    for (int j = tid; j < out_size; j += nth) out[j] = 0.0f;
    int warp = tid >> 5, lane = tid & 31, nwarps = nth >> 5;
    for (int s = warp; s < M; s += nwarps) {
        int a = ptr[s], b = ptr[s + 1];
        for (int i = a + lane; i < b; i += 32) g_seg[i] = s;
    }
}

// stage one weight matrix as fused 16B hi/lo quads; rowq = quads per row
static __device__ __forceinline__ void stage_w(char* smem, int offW,
                                               const float* __restrict__ W,
                                               int nrows, int nkt, int rowq,
                                               int kmax, int ncols, int t) {
    int entries = nrows * nkt * 4;
    for (int e = t; e < entries; e += NT) {
        int n = e / (nkt * 4), r = e % (nkt * 4), kt = r >> 2, i4 = r & 3;
        int k0 = kt * 16 + 2 * i4;
        float w0 = (k0     < kmax) ? W[(k0)     * ncols + n] : 0.f;
        float w1 = (k0 + 1 < kmax) ? W[(k0 + 1) * ncols + n] : 0.f;
        float w2 = (k0 + 8 < kmax) ? W[(k0 + 8) * ncols + n] : 0.f;
        float w3 = (k0 + 9 < kmax) ? W[(k0 + 9) * ncols + n] : 0.f;
        int off = (n * rowq + kt * 4 + i4) * 16;
        *(uint4*)(smem + offW + off) =
            make_uint4(pack_hi(w0, w1), pack_hi(w2, w3), pack_lo(w0, w1), pack_lo(w2, w3));
    }
}

__global__ __launch_bounds__(NT, 3)
void dag_mma_kernel(
    const float* __restrict__ x, const float* __restrict__ h_node,
    const float* __restrict__ W1, const float* __restrict__ b1,
    const float* __restrict__ W2, const float* __restrict__ b2,
    const float* __restrict__ W3, const float* __restrict__ b3,
    float* __restrict__ out, int N, int numChunks)
{
    extern __shared__ char smem[];
    const int t = threadIdx.x;

    stage_w(smem, OFF_W1, W1, 64, 3, 12, 40, 64, t);
    stage_w(smem, OFF_W2, W2, 64, 4, 20, 64, 64, t);
    stage_w(smem, OFF_W3, W3, 32, 4, 20, 64, 32, t);
    if (t < 64) {
        ((float*)(smem + OFF_B1))[t] = b1[t];
        ((float*)(smem + OFF_B2))[t] = b2[t];
    }
    if (t < 32) ((float*)(smem + OFF_B3))[t] = b3[t];
    __syncthreads();

    const float* b1s = (const float*)(smem + OFF_B1);
    const float* b2s = (const float*)(smem + OFF_B2);
    const float* b3s = (const float*)(smem + OFF_B3);

    const int lane = t & 31, wid = t >> 5;
    const int i4 = lane & 3, r4 = lane >> 2;
    const char* w1base = smem + OFF_W1 + r4 * 192 + i4 * 16;
    const char* w2base = smem + OFF_W2 + r4 * 320 + i4 * 16;
    const char* w3base = smem + OFF_W3 + r4 * 320 + i4 * 16;
    float* fbuf = (float*)(smem + OFF_FLUSH) + wid * (16 * 33);

    const int warpsTotal = gridDim.x * (NT / 32);
    const int warpGlobal = blockIdx.x * (NT / 32) + wid;

    float2 pA[6], pB[6];
    int pseg = -1;
    if (warpGlobal < numChunks) {
        prefetch_chunk(x, h_node, warpGlobal * CHUNK, N, r4, i4, pA, pB);
        int node = warpGlobal * CHUNK + lane;
        if (lane < CHUNK && node < N) pseg = g_seg[node];
    }

    for (int c = warpGlobal; c < numChunks; c += warpsTotal) {
        const int myseg = pseg;

        // ---------- Layer 1: [16 x 48] @ [48 x 64], bias in acc init ----------
        float acc1[8][4];
        #pragma unroll
        for (int nt = 0; nt < 8; nt++) {
            float2 bb = *(const float2*)(b1s + nt * 8 + 2 * i4);
            acc1[nt][0] = bb.x; acc1[nt][1] = bb.y;
            acc1[nt][2] = bb.x; acc1[nt][3] = bb.y;
        }

        #pragma unroll
        for (int kt = 0; kt < 3; kt++) {
            uint32_t ah[4], al[4];
            #pragma unroll
            for (int p = 0; p < 2; p++) {
                float2 fA = pA[kt * 2 + p], fB = pB[kt * 2 + p];
                ah[2 * p]     = pack_hi(fA.x, fA.y);
                ah[2 * p + 1] = pack_hi(fB.x, fB.y);
                al[2 * p]     = pack_lo(fA.x, fA.y);
                al[2 * p + 1] = pack_lo(fB.x, fB.y);
            }
            #pragma unroll
            for (int nt = 0; nt < 8; nt++) {
                uint4 q = *(const uint4*)(w1base + nt * 1536 + kt * 64);
                mma3(acc1[nt], ah, al, q);
            }
        }
        #pragma unroll
        for (int nt = 0; nt < 8; nt++) {
            acc1[nt][0] = fmaxf(acc1[nt][0], 0.0f);
            acc1[nt][1] = fmaxf(acc1[nt][1], 0.0f);
            acc1[nt][2] = fmaxf(acc1[nt][2], 0.0f);
            acc1[nt][3] = fmaxf(acc1[nt][3], 0.0f);
        }

        // ---- prefetch next chunk (hides under L2+L3+flush) ----
        {
            int cn = c + warpsTotal;
            if (cn < numChunks) {
                prefetch_chunk(x, h_node, cn * CHUNK, N, r4, i4, pA, pB);
                int node = cn * CHUNK + lane;
                pseg = (lane < CHUNK && node < N) ? g_seg[node] : -1;
            }
        }

        // ---------- Layer 2: [16 x 64] @ [64 x 64], bias in acc init ----------
        float acc2[8][4];
        #pragma unroll
        for (int nt = 0; nt < 8; nt++) {
            float2 bb = *(const float2*)(b2s + nt * 8 + 2 * i4);
            acc2[nt][0] = bb.x; acc2[nt][1] = bb.y;
            acc2[nt][2] = bb.x; acc2[nt][3] = bb.y;
        }

        #pragma unroll
        for (int kt = 0; kt < 4; kt++) {
            uint32_t ah[4], al[4];
            repack(acc1[2 * kt], acc1[2 * kt + 1], ah, al);
            #pragma unroll
            for (int nt = 0; nt < 8; nt++) {
                uint4 q = *(const uint4*)(w2base + nt * 2560 + kt * 64);
                mma3(acc2[nt], ah, al, q);
            }
        }
        #pragma unroll
        for (int nt = 0; nt < 8; nt++) {
            acc2[nt][0] = fmaxf(acc2[nt][0], 0.0f);
            acc2[nt][1] = fmaxf(acc2[nt][1], 0.0f);
            acc2[nt][2] = fmaxf(acc2[nt][2], 0.0f);
            acc2[nt][3] = fmaxf(acc2[nt][3], 0.0f);
        }

        // ---------- Layer 3: [16 x 64] @ [64 x 32], bias in acc init ----------
        float acc3[4][4];
        #pragma unroll
        for (int nt = 0; nt < 4; nt++) {
            float2 bb = *(const float2*)(b3s + nt * 8 + 2 * i4);
            acc3[nt][0] = bb.x; acc3[nt][1] = bb.y;
            acc3[nt][2] = bb.x; acc3[nt][3] = bb.y;
        }

        #pragma unroll
        for (int kt = 0; kt < 4; kt++) {
            uint32_t ah[4], al[4];
            repack(acc2[2 * kt], acc2[2 * kt + 1], ah, al);
            #pragma unroll
            for (int nt = 0; nt < 4; nt++) {
                uint4 q = *(const uint4*)(w3base + nt * 2560 + kt * 64);
                mma3(acc3[nt], ah, al, q);
            }
        }

        // ---------- segment flush (acc3 already includes bias) ----------
        const int s0 = __shfl_sync(0xffffffffu, myseg, 0);
        const unsigned vote = __ballot_sync(0xffffffffu, myseg == s0);
        if (s0 >= 0 && (vote & 0xffffu) == 0xffffu) {
            // FAST PATH: whole chunk in one segment; register-only reduction.
            float s[8];
            #pragma unroll
            for (int nt = 0; nt < 4; nt++) {
                s[2 * nt]     = acc3[nt][0] + acc3[nt][2];
                s[2 * nt + 1] = acc3[nt][1] + acc3[nt][3];
            }
            #pragma unroll
            for (int off = 4; off <= 16; off <<= 1)
                #pragma unroll
                for (int j = 0; j < 8; j++)
                    s[j] += __shfl_xor_sync(0xffffffffu, s[j], off);
            if (r4 == 0) {
                #pragma unroll
                for (int nt = 0; nt < 4; nt++) {
                    atomicAdd(&out[s0 * 32 + nt * 8 + 2 * i4],     s[2 * nt]);
                    atomicAdd(&out[s0 * 32 + nt * 8 + 2 * i4 + 1], s[2 * nt + 1]);
                }
            }
        } else {
            // SLOW PATH: run-length reduce via per-warp smem buffer
            #pragma unroll
            for (int nt = 0; nt < 4; nt++) {
                const int cc = nt * 8 + 2 * i4;
                fbuf[r4 * 33 + cc]           = acc3[nt][0];
                fbuf[r4 * 33 + cc + 1]       = acc3[nt][1];
                fbuf[(r4 + 8) * 33 + cc]     = acc3[nt][2];
                fbuf[(r4 + 8) * 33 + cc + 1] = acc3[nt][3];
            }
            __syncwarp();
            int cur = -1;
            float a = 0.0f;
            #pragma unroll 4
            for (int i = 0; i < CHUNK; i++) {
                int sv = __shfl_sync(0xffffffffu, myseg, i);
                float v = fbuf[i * 33 + lane];
                if (sv != cur) {
                    if (cur >= 0) atomicAdd(&out[cur * 32 + lane], a);
                    cur = sv; a = v;
                } else {
                    a += v;
                }
            }
            if (cur >= 0) atomicAdd(&out[cur * 32 + lane], a);
            __syncwarp();
        }
    }
}

extern "C" void kernel_launch(void* const* d_in, const int* in_sizes, int n_in,
                              void* d_out, int out_size) {
    const float* x      = (const float*)d_in[0];
    const float* h_node = (const float*)d_in[1];
    const float* W1     = (const float*)d_in[2];
    const float* b1     = (const float*)d_in[3];
    const float* W2     = (const float*)d_in[4];
    const float* b2     = (const float*)d_in[5];
    const float* W3     = (const float*)d_in[6];
    const float* b3     = (const float*)d_in[7];
    const int*   ptr    = (const int*)d_in[8];
    float* out = (float*)d_out;

    const int N = in_sizes[1] / 32;
    const int M = in_sizes[8] - 1;
    const int numChunks = (N + CHUNK - 1) / CHUNK;

    init_kernel<<<592, 256>>>(ptr, out, out_size, M);

    cudaFuncSetAttribute(dag_mma_kernel,
                         cudaFuncAttributeMaxDynamicSharedMemorySize, SMEM_BYTES);

    int dev = 0;
    cudaGetDevice(&dev);
    int sm_count = 148;
    cudaDeviceGetAttribute(&sm_count, cudaDevAttrMultiProcessorCount, dev);

    dag_mma_kernel<<<sm_count * 3, NT, SMEM_BYTES>>>(
        x, h_node, W1, b1, W2, b2, W3, b3, out, N, numChunks);
}

// round 15
// speedup vs baseline: 1.1630x; 1.1630x over previous
#include <cuda_runtime.h>
#include <cuda_bf16.h>
#include <cstdint>

#define NT 128
#define CHUNK 16

__device__ int g_seg[2000128];

// fused weight quads: entry (n,kt,i4) = 16B {bh0,bh1,bl0,bl1}
// W1 row stride 192B (12 quads); W2/W3 row stride 320B (20 quads)
#define OFF_W1   0        // 64*192 = 12288
#define OFF_W2   12288    // 64*320 = 20480
#define OFF_W3   32768    // 32*320 = 10240
#define OFF_B1   43008
#define OFF_B2   43264
#define OFF_B3   43520
#define OFF_FLUSH 43648   // 4 warps * 16*33*4 = 8448
#define SMEM_BYTES 52224

static __device__ __forceinline__ void mma_bf16(float c[4], const uint32_t a[4],
                                                uint32_t b0, uint32_t b1) {
    asm volatile(
        "mma.sync.aligned.m16n8k16.row.col.f32.bf16.bf16.f32 "
        "{%0,%1,%2,%3}, {%4,%5,%6,%7}, {%8,%9}, {%0,%1,%2,%3};"
        : "+f"(c[0]), "+f"(c[1]), "+f"(c[2]), "+f"(c[3])
        : "r"(a[0]), "r"(a[1]), "r"(a[2]), "r"(a[3]), "r"(b0), "r"(b1));
}
static __device__ __forceinline__ uint32_t pack_hi(float v0, float v1) {
    return __byte_perm(__float_as_uint(v0), __float_as_uint(v1), 0x7632);
}
static __device__ __forceinline__ uint32_t pack_lo(float v0, float v1) {
    float h0 = __uint_as_float(__float_as_uint(v0) & 0xFFFF0000u);
    float h1 = __uint_as_float(__float_as_uint(v1) & 0xFFFF0000u);
    __nv_bfloat162 p = __floats2bfloat162_rn(v0 - h0, v1 - h1);
    return *(uint32_t*)&p;
}
// 3-pass split MMA: hi*hi + hi*lo + lo*hi (fp32-accurate to ~2^-18)
static __device__ __forceinline__ void mma3(float c[4], const uint32_t ah[4],
                                            const uint32_t al[4], uint4 q) {
    mma_bf16(c, ah, q.x, q.y);
    mma_bf16(c, ah, q.z, q.w);
    mma_bf16(c, al, q.x, q.y);
}
static __device__ __forceinline__ void repack(const float* s0, const float* s1,
                                              uint32_t ah[4], uint32_t al[4]) {
    ah[0] = pack_hi(s0[0], s0[1]);  al[0] = pack_lo(s0[0], s0[1]);
    ah[1] = pack_hi(s0[2], s0[3]);  al[1] = pack_lo(s0[2], s0[3]);
    ah[2] = pack_hi(s1[0], s1[1]);  al[2] = pack_lo(s1[0], s1[1]);
    ah[3] = pack_hi(s1[2], s1[3]);  al[3] = pack_lo(s1[2], s1[3]);
}
static __device__ __forceinline__ float2 load_in(const float* __restrict__ x,
                                                 const float* __restrict__ h,
                                                 int row, int kk, int N) {
    float2 v = make_float2(0.f, 0.f);
    if (row < N) {
        if (kk < 8)       v = *(const float2*)(x + (size_t)row * 8 + kk);
        else if (kk < 40) v = *(const float2*)(h + (size_t)row * 32 + (kk - 8));
    }
    return v;
}
static __device__ __forceinline__ void prefetch_chunk(const float* __restrict__ x,
                                                      const float* __restrict__ h,
                                                      int base, int N, int r4, int i4,
                                                      float2 pA[6], float2 pB[6]) {
    #pragma unroll
    for (int kt = 0; kt < 3; kt++)
        #pragma unroll
        for (int p = 0; p < 2; p++) {
            int kk = kt * 16 + 2 * i4 + 8 * p;
            pA[kt * 2 + p] = load_in(x, h, base + r4, kk, N);
            pB[kt * 2 + p] = load_in(x, h, base + 8 + r4, kk, N);
        }
}

__global__ void init_kernel(const int* __restrict__ ptr, float* __restrict__ out,
                            int out_size, int M) {
    int tid = blockIdx.x * blockDim.x + threadIdx.x;
    int nth = gridDim.x * blockDim.x;
    for (int j = tid; j < out_size; j += nth) out[j] = 0.0f;
    int warp = tid >> 5, lane = tid & 31, nwarps = nth >> 5;
    for (int s = warp; s < M; s += nwarps) {
        int a = ptr[s], b = ptr[s + 1];
        for (int i = a + lane; i < b; i += 32) g_seg[i] = s;
    }
}

// stage one weight matrix as fused 16B hi/lo quads; rowq = quads per row
static __device__ __forceinline__ void stage_w(char* smem, int offW,
                                               const float* __restrict__ W,
                                               int nrows, int nkt, int rowq,
                                               int kmax, int ncols, int t) {
    int entries = nrows * nkt * 4;
    for (int e = t; e < entries; e += NT) {
        int n = e / (nkt * 4), r = e % (nkt * 4), kt = r >> 2, i4 = r & 3;
        int k0 = kt * 16 + 2 * i4;
        float w0 = (k0     < kmax) ? W[(k0)     * ncols + n] : 0.f;
        float w1 = (k0 + 1 < kmax) ? W[(k0 + 1) * ncols + n] : 0.f;
        float w2 = (k0 + 8 < kmax) ? W[(k0 + 8) * ncols + n] : 0.f;
        float w3 = (k0 + 9 < kmax) ? W[(k0 + 9) * ncols + n] : 0.f;
        int off = (n * rowq + kt * 4 + i4) * 16;
        *(uint4*)(smem + offW + off) =
            make_uint4(pack_hi(w0, w1), pack_hi(w2, w3), pack_lo(w0, w1), pack_lo(w2, w3));
    }
}

__global__ __launch_bounds__(NT, 4)
void dag_mma_kernel(
    const float* __restrict__ x, const float* __restrict__ h_node,
    const float* __restrict__ W1, const float* __restrict__ b1,
    const float* __restrict__ W2, const float* __restrict__ b2,
    const float* __restrict__ W3, const float* __restrict__ b3,
    float* __restrict__ out, int N, int numChunks)
{
    extern __shared__ char smem[];
    const int t = threadIdx.x;

    stage_w(smem, OFF_W1, W1, 64, 3, 12, 40, 64, t);
    stage_w(smem, OFF_W2, W2, 64, 4, 20, 64, 64, t);
    stage_w(smem, OFF_W3, W3, 32, 4, 20, 64, 32, t);
    if (t < 64) {
        ((float*)(smem + OFF_B1))[t] = b1[t];
        ((float*)(smem + OFF_B2))[t] = b2[t];
    }
    if (t < 32) ((float*)(smem + OFF_B3))[t] = b3[t];
    __syncthreads();

    const float* b1s = (const float*)(smem + OFF_B1);
    const float* b2s = (const float*)(smem + OFF_B2);
    const float* b3s = (const float*)(smem + OFF_B3);

    const int lane = t & 31, wid = t >> 5;
    const int i4 = lane & 3, r4 = lane >> 2;
    const char* w1base = smem + OFF_W1 + r4 * 192 + i4 * 16;
    const char* w2base = smem + OFF_W2 + r4 * 320 + i4 * 16;
    const char* w3base = smem + OFF_W3 + r4 * 320 + i4 * 16;
    float* fbuf = (float*)(smem + OFF_FLUSH) + wid * (16 * 33);

    const int warpsTotal = gridDim.x * (NT / 32);
    const int warpGlobal = blockIdx.x * (NT / 32) + wid;

    float2 pA[6], pB[6];
    int pseg = -1;
    if (warpGlobal < numChunks) {
        prefetch_chunk(x, h_node, warpGlobal * CHUNK, N, r4, i4, pA, pB);
        int node = warpGlobal * CHUNK + lane;
        if (lane < CHUNK && node < N) pseg = g_seg[node];
    }

    for (int c = warpGlobal; c < numChunks; c += warpsTotal) {
        const int myseg = pseg;

        // ---------- Layer 1: [16 x 48] @ [48 x 64], bias folded into acc ----------
        float acc1[8][4];
        #pragma unroll
        for (int nt = 0; nt < 8; nt++) {
            float2 bb = *(const float2*)(b1s + nt * 8 + 2 * i4);
            acc1[nt][0] = bb.x; acc1[nt][1] = bb.y;
            acc1[nt][2] = bb.x; acc1[nt][3] = bb.y;
        }

        #pragma unroll
        for (int kt = 0; kt < 3; kt++) {
            uint32_t ah[4], al[4];
            #pragma unroll
            for (int p = 0; p < 2; p++) {
                float2 fA = pA[kt * 2 + p], fB = pB[kt * 2 + p];
                ah[2 * p]     = pack_hi(fA.x, fA.y);
                ah[2 * p + 1] = pack_hi(fB.x, fB.y);
                al[2 * p]     = pack_lo(fA.x, fA.y);
                al[2 * p + 1] = pack_lo(fB.x, fB.y);
            }
            #pragma unroll
            for (int nt = 0; nt < 8; nt++) {
                uint4 q = *(const uint4*)(w1base + nt * 1536 + kt * 64);
                mma3(acc1[nt], ah, al, q);
            }
        }
        #pragma unroll
        for (int nt = 0; nt < 8; nt++) {
            acc1[nt][0] = fmaxf(acc1[nt][0], 0.0f);
            acc1[nt][1] = fmaxf(acc1[nt][1], 0.0f);
            acc1[nt][2] = fmaxf(acc1[nt][2], 0.0f);
            acc1[nt][3] = fmaxf(acc1[nt][3], 0.0f);
        }

        // ---- prefetch next chunk (hides under L2+L3+flush) ----
        {
            int cn = c + warpsTotal;
            if (cn < numChunks) {
                prefetch_chunk(x, h_node, cn * CHUNK, N, r4, i4, pA, pB);
                int node = cn * CHUNK + lane;
                pseg = (lane < CHUNK && node < N) ? g_seg[node] : -1;
            }
        }

        // ---------- Layer 2: [16 x 64] @ [64 x 64], bias folded ----------
        float acc2[8][4];
        #pragma unroll
        for (int nt = 0; nt < 8; nt++) {
            float2 bb = *(const float2*)(b2s + nt * 8 + 2 * i4);
            acc2[nt][0] = bb.x; acc2[nt][1] = bb.y;
            acc2[nt][2] = bb.x; acc2[nt][3] = bb.y;
        }

        #pragma unroll
        for (int kt = 0; kt < 4; kt++) {
            uint32_t ah[4], al[4];
            repack(acc1[2 * kt], acc1[2 * kt + 1], ah, al);
            #pragma unroll
            for (int nt = 0; nt < 8; nt++) {
                uint4 q = *(const uint4*)(w2base + nt * 2560 + kt * 64);
                mma3(acc2[nt], ah, al, q);
            }
        }
        #pragma unroll
        for (int nt = 0; nt < 8; nt++) {
            acc2[nt][0] = fmaxf(acc2[nt][0], 0.0f);
            acc2[nt][1] = fmaxf(acc2[nt][1], 0.0f);
            acc2[nt][2] = fmaxf(acc2[nt][2], 0.0f);
            acc2[nt][3] = fmaxf(acc2[nt][3], 0.0f);
        }

        // ---------- Layer 3: [16 x 64] @ [64 x 32], bias folded ----------
        float acc3[4][4];
        #pragma unroll
        for (int nt = 0; nt < 4; nt++) {
            float2 bb = *(const float2*)(b3s + nt * 8 + 2 * i4);
            acc3[nt][0] = bb.x; acc3[nt][1] = bb.y;
            acc3[nt][2] = bb.x; acc3[nt][3] = bb.y;
        }

        #pragma unroll
        for (int kt = 0; kt < 4; kt++) {
            uint32_t ah[4], al[4];
            repack(acc2[2 * kt], acc2[2 * kt + 1], ah, al);
            #pragma unroll
            for (int nt = 0; nt < 4; nt++) {
                uint4 q = *(const uint4*)(w3base + nt * 2560 + kt * 64);
                mma3(acc3[nt], ah, al, q);
            }
        }

        // ---------- segment flush (acc3 already includes bias) ----------
        const int s0 = __shfl_sync(0xffffffffu, myseg, 0);
        const unsigned vote = __ballot_sync(0xffffffffu, myseg == s0);
        if (s0 >= 0 && (vote & 0xffffu) == 0xffffu) {
            // FAST PATH: whole chunk in one segment; register-only reduction.
            float s[8];
            #pragma unroll
            for (int nt = 0; nt < 4; nt++) {
                s[2 * nt]     = acc3[nt][0] + acc3[nt][2];
                s[2 * nt + 1] = acc3[nt][1] + acc3[nt][3];
            }
            #pragma unroll
            for (int off = 4; off <= 16; off <<= 1)
                #pragma unroll
                for (int j = 0; j < 8; j++)
                    s[j] += __shfl_xor_sync(0xffffffffu, s[j], off);
            if (r4 == 0) {
                #pragma unroll
                for (int nt = 0; nt < 4; nt++) {
                    atomicAdd(&out[s0 * 32 + nt * 8 + 2 * i4],     s[2 * nt]);
                    atomicAdd(&out[s0 * 32 + nt * 8 + 2 * i4 + 1], s[2 * nt + 1]);
                }
            }
        } else {
            // SLOW PATH: run-length reduce via per-warp smem buffer
            #pragma unroll
            for (int nt = 0; nt < 4; nt++) {
                const int cc = nt * 8 + 2 * i4;
                fbuf[r4 * 33 + cc]           = acc3[nt][0];
                fbuf[r4 * 33 + cc + 1]       = acc3[nt][1];
                fbuf[(r4 + 8) * 33 + cc]     = acc3[nt][2];
                fbuf[(r4 + 8) * 33 + cc + 1] = acc3[nt][3];
            }
            __syncwarp();
            int cur = -1;
            float a = 0.0f;
            #pragma unroll 4
            for (int i = 0; i < CHUNK; i++) {
                int sv = __shfl_sync(0xffffffffu, myseg, i);
                float v = fbuf[i * 33 + lane];
                if (sv != cur) {
                    if (cur >= 0) atomicAdd(&out[cur * 32 + lane], a);
                    cur = sv; a = v;
                } else {
                    a += v;
                }
            }
            if (cur >= 0) atomicAdd(&out[cur * 32 + lane], a);
            __syncwarp();
        }
    }
}

extern "C" void kernel_launch(void* const* d_in, const int* in_sizes, int n_in,
                              void* d_out, int out_size) {
    const float* x      = (const float*)d_in[0];
    const float* h_node = (const float*)d_in[1];
    const float* W1     = (const float*)d_in[2];
    const float* b1     = (const float*)d_in[3];
    const float* W2     = (const float*)d_in[4];
    const float* b2     = (const float*)d_in[5];
    const float* W3     = (const float*)d_in[6];
    const float* b3     = (const float*)d_in[7];
    const int*   ptr    = (const int*)d_in[8];
    float* out = (float*)d_out;

    const int N = in_sizes[1] / 32;
    const int M = in_sizes[8] - 1;
    const int numChunks = (N + CHUNK - 1) / CHUNK;

    init_kernel<<<592, 256>>>(ptr, out, out_size, M);

    cudaFuncSetAttribute(dag_mma_kernel,
                         cudaFuncAttributeMaxDynamicSharedMemorySize, SMEM_BYTES);

    int dev = 0;
    cudaGetDevice(&dev);
    int sm_count = 148;
    cudaDeviceGetAttribute(&sm_count, cudaDevAttrMultiProcessorCount, dev);

    dag_mma_kernel<<<sm_count * 4, NT, SMEM_BYTES>>>(
        x, h_node, W1, b1, W2, b2, W3, b3, out, N, numChunks);
}

// round 17
// speedup vs baseline: 1.5149x; 1.3025x over previous
#include <cuda_runtime.h>
#include <cuda_fp16.h>
#include <cstdint>

#define NT 128
#define CHUNK 16

__device__ int g_seg[2000128];

// single-digit f16 weight quads: entry (n,kt,i4) = 8B {h2(w0,w1), h2(w2,w3)}
// row stride 160B (20 entry slots) -> r4*40 words ≡ 8 mod 32: ≤2-way on LDS.64
#define OFF_W1   0        // 64*160 = 10240
#define OFF_W2   10240    // 64*160 = 10240
#define OFF_W3   20480    // 32*160 = 5120
#define OFF_B1   25600
#define OFF_B2   25856
#define OFF_B3   26112
#define OFF_FLUSH 26240   // 4 warps * 16*33*4 = 8448
#define SMEM_BYTES 34688

static __device__ __forceinline__ void mma_f16(float c[4], const uint32_t a[4],
                                               uint32_t b0, uint32_t b1) {
    asm volatile(
        "mma.sync.aligned.m16n8k16.row.col.f32.f16.f16.f32 "
        "{%0,%1,%2,%3}, {%4,%5,%6,%7}, {%8,%9}, {%0,%1,%2,%3};"
        : "+f"(c[0]), "+f"(c[1]), "+f"(c[2]), "+f"(c[3])
        : "r"(a[0]), "r"(a[1]), "r"(a[2]), "r"(a[3]), "r"(b0), "r"(b1));
}
static __device__ __forceinline__ uint32_t h2bits(__half2 h) {
    return *(uint32_t*)&h;
}
// f16 2-digit split of a float pair: hi = f16(v), lo = f16(v - hi) (exact residual)
static __device__ __forceinline__ void splitf16(float v0, float v1,
                                                uint32_t& hi, uint32_t& lo) {
    __half2 h = __floats2half2_rn(v0, v1);
    float2 f = __half22float2(h);
    __half2 l = __floats2half2_rn(v0 - f.x, v1 - f.y);
    hi = h2bits(h);
    lo = h2bits(l);
}
// 2-pass split MMA: (ahi + alo) * b ; weight is single f16 digit
static __device__ __forceinline__ void mma2(float c[4], const uint32_t ah[4],
                                            const uint32_t al[4], uint2 b) {
    mma_f16(c, ah, b.x, b.y);
    mma_f16(c, al, b.x, b.y);
}
static __device__ __forceinline__ void repack(const float* s0, const float* s1,
                                              uint32_t ah[4], uint32_t al[4]) {
    splitf16(s0[0], s0[1], ah[0], al[0]);
    splitf16(s0[2], s0[3], ah[1], al[1]);
    splitf16(s1[0], s1[1], ah[2], al[2]);
    splitf16(s1[2], s1[3], ah[3], al[3]);
}
static __device__ __forceinline__ float2 load_in(const float* __restrict__ x,
                                                 const float* __restrict__ h,
                                                 int row, int kk, int N) {
    float2 v = make_float2(0.f, 0.f);
    if (row < N) {
        if (kk < 8)       v = *(const float2*)(x + (size_t)row * 8 + kk);
        else if (kk < 40) v = *(const float2*)(h + (size_t)row * 32 + (kk - 8));
    }
    return v;
}
static __device__ __forceinline__ void prefetch_chunk(const float* __restrict__ x,
                                                      const float* __restrict__ h,
                                                      int base, int N, int r4, int i4,
                                                      float2 pA[6], float2 pB[6]) {
    #pragma unroll
    for (int kt = 0; kt < 3; kt++)
        #pragma unroll
        for (int p = 0; p < 2; p++) {
            int kk = kt * 16 + 2 * i4 + 8 * p;
            pA[kt * 2 + p] = load_in(x, h, base + r4, kk, N);
            pB[kt * 2 + p] = load_in(x, h, base + 8 + r4, kk, N);
        }
}

__global__ void init_kernel(const int* __restrict__ ptr, float* __restrict__ out,
                            int out_size, int M) {
    int tid = blockIdx.x * blockDim.x + threadIdx.x;
    int nth = gridDim.x * blockDim.x;
    for (int j = tid; j < out_size; j += nth) out[j] = 0.0f;
    int warp = tid >> 5, lane = tid & 31, nwarps = nth >> 5;
    for (int s = warp; s < M; s += nwarps) {
        int a = ptr[s], b = ptr[s + 1];
        for (int i = a + lane; i < b; i += 32) g_seg[i] = s;
    }
}

// stage weights as single-digit f16 quads (8B each)
static __device__ __forceinline__ void stage_w(char* smem, int offW,
                                               const float* __restrict__ W,
                                               int nrows, int nkt,
                                               int kmax, int ncols, int t) {
    int entries = nrows * nkt * 4;
    for (int e = t; e < entries; e += NT) {
        int n = e / (nkt * 4), r = e % (nkt * 4), kt = r >> 2, i4 = r & 3;
        int k0 = kt * 16 + 2 * i4;
        float w0 = (k0     < kmax) ? W[(k0)     * ncols + n] : 0.f;
        float w1 = (k0 + 1 < kmax) ? W[(k0 + 1) * ncols + n] : 0.f;
        float w2 = (k0 + 8 < kmax) ? W[(k0 + 8) * ncols + n] : 0.f;
        float w3 = (k0 + 9 < kmax) ? W[(k0 + 9) * ncols + n] : 0.f;
        int off = (n * 20 + kt * 4 + i4) * 8;
        *(uint2*)(smem + offW + off) =
            make_uint2(h2bits(__floats2half2_rn(w0, w1)),
                       h2bits(__floats2half2_rn(w2, w3)));
    }
}

__global__ __launch_bounds__(NT, 4)
void dag_mma_kernel(
    const float* __restrict__ x, const float* __restrict__ h_node,
    const float* __restrict__ W1, const float* __restrict__ b1,
    const float* __restrict__ W2, const float* __restrict__ b2,
    const float* __restrict__ W3, const float* __restrict__ b3,
    float* __restrict__ out, int N, int numChunks)
{
    extern __shared__ char smem[];
    const int t = threadIdx.x;

    stage_w(smem, OFF_W1, W1, 64, 3, 40, 64, t);
    stage_w(smem, OFF_W2, W2, 64, 4, 64, 64, t);
    stage_w(smem, OFF_W3, W3, 32, 4, 64, 32, t);
    if (t < 64) {
        ((float*)(smem + OFF_B1))[t] = b1[t];
        ((float*)(smem + OFF_B2))[t] = b2[t];
    }
    if (t < 32) ((float*)(smem + OFF_B3))[t] = b3[t];
    __syncthreads();

    const float* b1s = (const float*)(smem + OFF_B1);
    const float* b2s = (const float*)(smem + OFF_B2);
    const float* b3s = (const float*)(smem + OFF_B3);

    const int lane = t & 31, wid = t >> 5;
    const int i4 = lane & 3, r4 = lane >> 2;
    const char* w1base = smem + OFF_W1 + r4 * 160 + i4 * 8;
    const char* w2base = smem + OFF_W2 + r4 * 160 + i4 * 8;
    const char* w3base = smem + OFF_W3 + r4 * 160 + i4 * 8;
    float* fbuf = (float*)(smem + OFF_FLUSH) + wid * (16 * 33);

    const int warpsTotal = gridDim.x * (NT / 32);
    const int warpGlobal = blockIdx.x * (NT / 32) + wid;

    float2 pA[6], pB[6];
    int pseg = -1;
    if (warpGlobal < numChunks) {
        prefetch_chunk(x, h_node, warpGlobal * CHUNK, N, r4, i4, pA, pB);
        int node = warpGlobal * CHUNK + lane;
        if (lane < CHUNK && node < N) pseg = g_seg[node];
    }

    for (int c = warpGlobal; c < numChunks; c += warpsTotal) {
        const int myseg = pseg;

        // ---------- Layer 1: [16 x 48] @ [48 x 64], bias folded ----------
        float acc1[8][4];
        #pragma unroll
        for (int nt = 0; nt < 8; nt++) {
            float2 bb = *(const float2*)(b1s + nt * 8 + 2 * i4);
            acc1[nt][0] = bb.x; acc1[nt][1] = bb.y;
            acc1[nt][2] = bb.x; acc1[nt][3] = bb.y;
        }

        #pragma unroll
        for (int kt = 0; kt < 3; kt++) {
            uint32_t ah[4], al[4];
            #pragma unroll
            for (int p = 0; p < 2; p++) {
                float2 fA = pA[kt * 2 + p], fB = pB[kt * 2 + p];
                splitf16(fA.x, fA.y, ah[2 * p],     al[2 * p]);
                splitf16(fB.x, fB.y, ah[2 * p + 1], al[2 * p + 1]);
            }
            #pragma unroll
            for (int nt = 0; nt < 8; nt++) {
                uint2 q = *(const uint2*)(w1base + nt * 1280 + kt * 32);
                mma2(acc1[nt], ah, al, q);
            }
        }
        #pragma unroll
        for (int nt = 0; nt < 8; nt++) {
            acc1[nt][0] = fmaxf(acc1[nt][0], 0.0f);
            acc1[nt][1] = fmaxf(acc1[nt][1], 0.0f);
            acc1[nt][2] = fmaxf(acc1[nt][2], 0.0f);
            acc1[nt][3] = fmaxf(acc1[nt][3], 0.0f);
        }

        // ---- prefetch next chunk (hides under L2+L3+flush) ----
        {
            int cn = c + warpsTotal;
            if (cn < numChunks) {
                prefetch_chunk(x, h_node, cn * CHUNK, N, r4, i4, pA, pB);
                int node = cn * CHUNK + lane;
                pseg = (lane < CHUNK && node < N) ? g_seg[node] : -1;
            }
        }

        // ---------- Layer 2: [16 x 64] @ [64 x 64], bias folded ----------
        float acc2[8][4];
        #pragma unroll
        for (int nt = 0; nt < 8; nt++) {
            float2 bb = *(const float2*)(b2s + nt * 8 + 2 * i4);
            acc2[nt][0] = bb.x; acc2[nt][1] = bb.y;
            acc2[nt][2] = bb.x; acc2[nt][3] = bb.y;
        }

        #pragma unroll
        for (int kt = 0; kt < 4; kt++) {
            uint32_t ah[4], al[4];
            repack(acc1[2 * kt], acc1[2 * kt + 1], ah, al);
            #pragma unroll
            for (int nt = 0; nt < 8; nt++) {
                uint2 q = *(const uint2*)(w2base + nt * 1280 + kt * 32);
                mma2(acc2[nt], ah, al, q);
            }
        }
        #pragma unroll
        for (int nt = 0; nt < 8; nt++) {
            acc2[nt][0] = fmaxf(acc2[nt][0], 0.0f);
            acc2[nt][1] = fmaxf(acc2[nt][1], 0.0f);
            acc2[nt][2] = fmaxf(acc2[nt][2], 0.0f);
            acc2[nt][3] = fmaxf(acc2[nt][3], 0.0f);
        }

        // ---------- Layer 3: [16 x 64] @ [64 x 32], bias folded ----------
        float acc3[4][4];
        #pragma unroll
        for (int nt = 0; nt < 4; nt++) {
            float2 bb = *(const float2*)(b3s + nt * 8 + 2 * i4);
            acc3[nt][0] = bb.x; acc3[nt][1] = bb.y;
            acc3[nt][2] = bb.x; acc3[nt][3] = bb.y;
        }

        #pragma unroll
        for (int kt = 0; kt < 4; kt++) {
            uint32_t ah[4], al[4];
            repack(acc2[2 * kt], acc2[2 * kt + 1], ah, al);
            #pragma unroll
            for (int nt = 0; nt < 4; nt++) {
                uint2 q = *(const uint2*)(w3base + nt * 1280 + kt * 32);
                mma2(acc3[nt], ah, al, q);
            }
        }

        // ---------- segment flush (acc3 already includes bias) ----------
        const int s0 = __shfl_sync(0xffffffffu, myseg, 0);
        const unsigned vote = __ballot_sync(0xffffffffu, myseg == s0);
        if (s0 >= 0 && (vote & 0xffffu) == 0xffffu) {
            // FAST PATH: whole chunk in one segment; register-only reduction.
            float s[8];
            #pragma unroll
            for (int nt = 0; nt < 4; nt++) {
                s[2 * nt]     = acc3[nt][0] + acc3[nt][2];
                s[2 * nt + 1] = acc3[nt][1] + acc3[nt][3];
            }
            #pragma unroll
            for (int off = 4; off <= 16; off <<= 1)
                #pragma unroll
                for (int j = 0; j < 8; j++)
                    s[j] += __shfl_xor_sync(0xffffffffu, s[j], off);
            if (r4 == 0) {
                #pragma unroll
                for (int nt = 0; nt < 4; nt++) {
                    atomicAdd(&out[s0 * 32 + nt * 8 + 2 * i4],     s[2 * nt]);
                    atomicAdd(&out[s0 * 32 + nt * 8 + 2 * i4 + 1], s[2 * nt + 1]);
                }
            }
        } else {
            // SLOW PATH: run-length reduce via per-warp smem buffer
            #pragma unroll
            for (int nt = 0; nt < 4; nt++) {
                const int cc = nt * 8 + 2 * i4;
                fbuf[r4 * 33 + cc]           = acc3[nt][0];
                fbuf[r4 * 33 + cc + 1]       = acc3[nt][1];
                fbuf[(r4 + 8) * 33 + cc]     = acc3[nt][2];
                fbuf[(r4 + 8) * 33 + cc + 1] = acc3[nt][3];
            }
            __syncwarp();
            int cur = -1;
            float a = 0.0f;
            #pragma unroll 4
            for (int i = 0; i < CHUNK; i++) {
                int sv = __shfl_sync(0xffffffffu, myseg, i);
                float v = fbuf[i * 33 + lane];
                if (sv != cur) {
                    if (cur >= 0) atomicAdd(&out[cur * 32 + lane], a);
                    cur = sv; a = v;
                } else {
                    a += v;
                }
            }
            if (cur >= 0) atomicAdd(&out[cur * 32 + lane], a);
            __syncwarp();
        }
    }
}

extern "C" void kernel_launch(void* const* d_in, const int* in_sizes, int n_in,
                              void* d_out, int out_size) {
    const float* x      = (const float*)d_in[0];
    const float* h_node = (const float*)d_in[1];
    const float* W1     = (const float*)d_in[2];
    const float* b1     = (const float*)d_in[3];
    const float* W2     = (const float*)d_in[4];
    const float* b2     = (const float*)d_in[5];
    const float* W3     = (const float*)d_in[6];
    const float* b3     = (const float*)d_in[7];
    const int*   ptr    = (const int*)d_in[8];
    float* out = (float*)d_out;

    const int N = in_sizes[1] / 32;
    const int M = in_sizes[8] - 1;
    const int numChunks = (N + CHUNK - 1) / CHUNK;

    init_kernel<<<592, 256>>>(ptr, out, out_size, M);

    cudaFuncSetAttribute(dag_mma_kernel,
                         cudaFuncAttributeMaxDynamicSharedMemorySize, SMEM_BYTES);

    int dev = 0;
    cudaGetDevice(&dev);
    int sm_count = 148;
    cudaDeviceGetAttribute(&sm_count, cudaDevAttrMultiProcessorCount, dev);

    dag_mma_kernel<<<sm_count * 4, NT, SMEM_BYTES>>>(
        x, h_node, W1, b1, W2, b2, W3, b3, out, N, numChunks);
}